// round 1
// baseline (speedup 1.0000x reference)
#include <cuda_runtime.h>

// ---------------- problem constants (fixed by the dataset) ----------------
#define NB    240          // batch
#define NS    64           // seq len
#define NHID  768          // hidden
#define NH    12           // heads
#define HD    64           // head dim
#define L0    384          // slot-cache len
#define L1    128          // per-example cache len
#define LTOT  576          // L0 + L1 + NS
#define NCHUNK 9           // 576 / 64

// q scratch in [b, h, s, d] layout (device global: allocation-free scratch)
__device__ float g_q[(size_t)NB * NH * NS * HD];

// =====================================================================
// QKV projection: out[m,n] = sum_k hidden[m,k] * W[n,k] + bias[n]
// M=15360, K=768, N=768 per matrix (q,k,v selected by blockIdx.y range).
// 64x64 output tile, BK=16, 4x4 per-thread register tile, 256 threads.
// Smem tiles stored transposed [kk][r] with stride 68 -> aligned float4
// reads in the inner loop, conflict-free.
// =====================================================================
__global__ __launch_bounds__(256) void qkv_gemm_kernel(
    const float* __restrict__ hidden,
    const float* __restrict__ Wq, const float* __restrict__ bq,
    const float* __restrict__ Wk, const float* __restrict__ bk,
    const float* __restrict__ Wv, const float* __restrict__ bv,
    float* __restrict__ out_k, float* __restrict__ out_v)
{
    __shared__ float As[16 * 68];
    __shared__ float Bs[16 * 68];

    const int m0   = blockIdx.x * 64;
    const int n0g  = blockIdx.y * 64;        // 0 .. 2303
    const int mat  = n0g / NHID;             // 0=q, 1=k, 2=v
    const int n0   = n0g - mat * NHID;

    const float* W  = (mat == 0) ? Wq : (mat == 1) ? Wk : Wv;
    const float* bi = (mat == 0) ? bq : (mat == 1) ? bk : bv;

    const int tid = threadIdx.x;
    const int tx  = tid & 15;
    const int ty  = tid >> 4;
    const int lr  = tid >> 2;                // 0..63 (tile row for loads)
    const int lk  = (tid & 3) << 2;          // 0,4,8,12 (k offset for loads)

    float acc[4][4];
#pragma unroll
    for (int i = 0; i < 4; i++)
#pragma unroll
        for (int j = 0; j < 4; j++) acc[i][j] = 0.f;

    const float* aptr = hidden + (size_t)(m0 + lr) * NHID + lk;
    const float* bptr = W      + (size_t)(n0 + lr) * NHID + lk;

    for (int k0 = 0; k0 < NHID; k0 += 16) {
        float4 av = *(const float4*)(aptr + k0);
        float4 wv = *(const float4*)(bptr + k0);
        As[(lk + 0) * 68 + lr] = av.x;
        As[(lk + 1) * 68 + lr] = av.y;
        As[(lk + 2) * 68 + lr] = av.z;
        As[(lk + 3) * 68 + lr] = av.w;
        Bs[(lk + 0) * 68 + lr] = wv.x;
        Bs[(lk + 1) * 68 + lr] = wv.y;
        Bs[(lk + 2) * 68 + lr] = wv.z;
        Bs[(lk + 3) * 68 + lr] = wv.w;
        __syncthreads();

#pragma unroll
        for (int kk = 0; kk < 16; kk++) {
            float4 a4 = *(const float4*)&As[kk * 68 + 4 * ty];
            float4 b4 = *(const float4*)&Bs[kk * 68 + 4 * tx];
            float a[4] = {a4.x, a4.y, a4.z, a4.w};
            float b[4] = {b4.x, b4.y, b4.z, b4.w};
#pragma unroll
            for (int i = 0; i < 4; i++)
#pragma unroll
                for (int j = 0; j < 4; j++)
                    acc[i][j] += a[i] * b[j];
        }
        __syncthreads();
    }

    // epilogue: add bias, scatter into [b, h, s, d] head layout
#pragma unroll
    for (int i = 0; i < 4; i++) {
        const int m = m0 + 4 * ty + i;
        const int b = m >> 6;               // m / 64
        const int s = m & 63;
#pragma unroll
        for (int j = 0; j < 4; j++) {
            const int nn = n0 + 4 * tx + j;
            const float val = acc[i][j] + bi[nn];
            const int h = nn >> 6;
            const int d = nn & 63;
            const size_t idx = (((size_t)b * NH + h) * NS + s) * HD + d;
            if (mat == 0)      g_q[idx]   = val;
            else if (mat == 1) out_k[idx] = val;
            else               out_v[idx] = val;
        }
    }
}

// =====================================================================
// Fused cache attention. One block per (b, h). 256 threads = 8 warps,
// warp w owns query rows 8w..8w+7.
// Keys/values streamed in 64-key chunks: chunks 0-5 = c0[b%8], 6-7 = c1[b],
// 8 = self k/v (read back from d_out). Full 64x576 score matrix in smem,
// exact softmax with mask, then PV accumulation.
// =====================================================================
__global__ __launch_bounds__(256) void attn_kernel(
    const float* __restrict__ mask,
    const float* __restrict__ c0k, const float* __restrict__ c0v,
    const float* __restrict__ c1k, const float* __restrict__ c1v,
    const float* __restrict__ kself, const float* __restrict__ vself,
    float* __restrict__ outctx)
{
    extern __shared__ float sm[];
    float* q_s    = sm;                      // [64][64]              4096
    float* kv_s   = q_s + 64 * 64;           // K^T [d][65] / V [j][64] 4352
    float* sc     = kv_s + 64 * 68;          // [64][576]             36864
    float* mask_s = sc + 64 * 576;           // [576]

    const int bh   = blockIdx.x;
    const int b    = bh / NH;
    const int h    = bh - b * NH;
    const int tid  = threadIdx.x;
    const int lane = tid & 31;
    const int w    = tid >> 5;
    const int r0   = w * 8;

    // ---- load q tile and mask ----
    {
        const float* qptr = g_q + (size_t)bh * NS * HD;
        const int r  = tid >> 4;
        const int d4 = (tid & 15) << 2;
        for (int rr = r; rr < 64; rr += 16)
            *(float4*)&q_s[rr * 64 + d4] = *(const float4*)&qptr[rr * HD + d4];
        for (int i = tid; i < LTOT; i += 256)
            mask_s[i] = mask[(size_t)b * LTOT + i];
    }

    const float* c0kb = c0k + (((size_t)(b & 7) * NH + h)) * L0 * HD;
    const float* c0vb = c0v + (((size_t)(b & 7) * NH + h)) * L0 * HD;
    const float* c1kb = c1k + (size_t)bh * L1 * HD;
    const float* c1vb = c1v + (size_t)bh * L1 * HD;
    const float* ksb  = kself + (size_t)bh * NS * HD;
    const float* vsb  = vself + (size_t)bh * NS * HD;

    // ---- phase 1: scores ----
    for (int c = 0; c < NCHUNK; c++) {
        const float* ksrc = (c < 6) ? (c0kb + c * 64 * HD)
                         : (c < 8) ? (c1kb + (c - 6) * 64 * HD)
                                   : ksb;
        __syncthreads();
        {   // load K^T tile: kv_s[d*65 + j], pad 65 -> conflict-light
            const int j0 = tid >> 4;
            const int d4 = (tid & 15) << 2;
            for (int j = j0; j < 64; j += 16) {
                float4 k4 = *(const float4*)&ksrc[j * HD + d4];
                kv_s[(d4 + 0) * 65 + j] = k4.x;
                kv_s[(d4 + 1) * 65 + j] = k4.y;
                kv_s[(d4 + 2) * 65 + j] = k4.z;
                kv_s[(d4 + 3) * 65 + j] = k4.w;
            }
        }
        __syncthreads();

        float acc0[8], acc1[8];
#pragma unroll
        for (int r = 0; r < 8; r++) { acc0[r] = 0.f; acc1[r] = 0.f; }

#pragma unroll
        for (int dd = 0; dd < 16; dd++) {
            const int d = dd * 4;
            float k00 = kv_s[(d + 0) * 65 + lane];
            float k01 = kv_s[(d + 1) * 65 + lane];
            float k02 = kv_s[(d + 2) * 65 + lane];
            float k03 = kv_s[(d + 3) * 65 + lane];
            float k10 = kv_s[(d + 0) * 65 + lane + 32];
            float k11 = kv_s[(d + 1) * 65 + lane + 32];
            float k12 = kv_s[(d + 2) * 65 + lane + 32];
            float k13 = kv_s[(d + 3) * 65 + lane + 32];
#pragma unroll
            for (int r = 0; r < 8; r++) {
                float4 q4 = *(const float4*)&q_s[(r0 + r) * 64 + d];
                acc0[r] += q4.x * k00 + q4.y * k01 + q4.z * k02 + q4.w * k03;
                acc1[r] += q4.x * k10 + q4.y * k11 + q4.z * k12 + q4.w * k13;
            }
        }
#pragma unroll
        for (int r = 0; r < 8; r++) {
            sc[(r0 + r) * 576 + c * 64 + lane]      = acc0[r] * 0.125f;
            sc[(r0 + r) * 576 + c * 64 + lane + 32] = acc1[r] * 0.125f;
        }
    }

    // ---- phase 2: softmax (per warp, its own 8 rows; no cross-warp dep) ----
    float rsum[8];
#pragma unroll
    for (int r = 0; r < 8; r++) {
        const int row = r0 + r;
        float vals[18];
        float mx = -1e30f;
#pragma unroll
        for (int i = 0; i < 18; i++) {
            const int col = lane + 32 * i;
            float v = sc[row * 576 + col] + mask_s[col];
            vals[i] = v;
            mx = fmaxf(mx, v);
        }
#pragma unroll
        for (int o = 16; o > 0; o >>= 1)
            mx = fmaxf(mx, __shfl_xor_sync(0xFFFFFFFFu, mx, o));
        float s = 0.f;
#pragma unroll
        for (int i = 0; i < 18; i++) {
            const int col = lane + 32 * i;
            float p = __expf(vals[i] - mx);
            sc[row * 576 + col] = p;
            s += p;
        }
#pragma unroll
        for (int o = 16; o > 0; o >>= 1)
            s += __shfl_xor_sync(0xFFFFFFFFu, s, o);
        rsum[r] = 1.f / s;
    }

    // ---- phase 3: ctx = P @ V ----
    float ctx0[8], ctx1[8];
#pragma unroll
    for (int r = 0; r < 8; r++) { ctx0[r] = 0.f; ctx1[r] = 0.f; }

    for (int c = 0; c < NCHUNK; c++) {
        const float* vsrc = (c < 6) ? (c0vb + c * 64 * HD)
                         : (c < 8) ? (c1vb + (c - 6) * 64 * HD)
                                   : vsb;
        __syncthreads();
        {   // load V tile natural layout [j][64]
            const int j0 = tid >> 4;
            const int d4 = (tid & 15) << 2;
            for (int j = j0; j < 64; j += 16)
                *(float4*)&kv_s[j * 64 + d4] = *(const float4*)&vsrc[j * HD + d4];
        }
        __syncthreads();

#pragma unroll 4
        for (int j = 0; j < 64; j++) {
            float v0 = kv_s[j * 64 + lane];
            float v1 = kv_s[j * 64 + lane + 32];
#pragma unroll
            for (int r = 0; r < 8; r++) {
                float p = sc[(r0 + r) * 576 + c * 64 + j];
                ctx0[r] += p * v0;
                ctx1[r] += p * v1;
            }
        }
    }

    // ---- write ctx -> out[b, s, h*64 + d] ----
#pragma unroll
    for (int r = 0; r < 8; r++) {
        const int row = r0 + r;
        float* o = outctx + ((size_t)b * NS + row) * NHID + h * HD;
        o[lane]      = ctx0[r] * rsum[r];
        o[lane + 32] = ctx1[r] * rsum[r];
    }
}

// =====================================================================
// Host launcher
// =====================================================================
extern "C" void kernel_launch(void* const* d_in, const int* in_sizes, int n_in,
                              void* d_out, int out_size)
{
    const float* hidden = (const float*)d_in[0];
    const float* mask   = (const float*)d_in[1];
    const float* Wq     = (const float*)d_in[2];
    const float* bq     = (const float*)d_in[3];
    const float* Wk     = (const float*)d_in[4];
    const float* bk     = (const float*)d_in[5];
    const float* Wv     = (const float*)d_in[6];
    const float* bv     = (const float*)d_in[7];
    const float* c0k    = (const float*)d_in[8];
    const float* c0v    = (const float*)d_in[9];
    const float* c1k    = (const float*)d_in[10];
    const float* c1v    = (const float*)d_in[11];

    float* out   = (float*)d_out;
    const size_t sect = (size_t)NB * NS * NHID;  // 11,796,480
    float* out_k = out + sect;
    float* out_v = out + 2 * sect;

    const int attn_smem = (64 * 64 + 64 * 68 + 64 * 576 + 576) * 4;  // 183552 B
    cudaFuncSetAttribute(attn_kernel,
                         cudaFuncAttributeMaxDynamicSharedMemorySize, attn_smem);

    dim3 ggrid(NB * NS / 64, 3 * NHID / 64);   // (240, 36)
    qkv_gemm_kernel<<<ggrid, 256>>>(hidden, Wq, bq, Wk, bk, Wv, bv, out_k, out_v);

    attn_kernel<<<NB * NH, 256, attn_smem>>>(mask, c0k, c0v, c1k, c1v,
                                             out_k, out_v, out);
}

// round 2
// speedup vs baseline: 2.2742x; 2.2742x over previous
#include <cuda_runtime.h>
#include <cstdint>

// ---------------- problem constants (fixed by the dataset) ----------------
#define NB    240
#define NS    64
#define NHID  768
#define NH    12
#define HD    64
#define L0    384
#define L1    128
#define LTOT  576
#define NCHUNK 9

// q scratch in [b, h, s, d] layout
__device__ float g_q[(size_t)NB * NH * NS * HD];

// ---------------- tf32 helpers ----------------
__device__ __forceinline__ uint32_t f2tf(float x) {
    uint32_t r;
    asm("cvt.rna.tf32.f32 %0, %1;" : "=r"(r) : "f"(x));
    return r;
}
__device__ __forceinline__ float f2tf_f(float x) { return __uint_as_float(f2tf(x)); }
__device__ __forceinline__ uint32_t fu(float x) { return __float_as_uint(x); }

#define MMA_TF32(c, a, b0, b1)                                              \
    asm volatile(                                                           \
        "mma.sync.aligned.m16n8k8.row.col.f32.tf32.tf32.f32 "               \
        "{%0,%1,%2,%3}, {%4,%5,%6,%7}, {%8,%9}, {%0,%1,%2,%3};\n"           \
        : "+f"((c)[0]), "+f"((c)[1]), "+f"((c)[2]), "+f"((c)[3])            \
        : "r"((a)[0]), "r"((a)[1]), "r"((a)[2]), "r"((a)[3]),               \
          "r"(b0), "r"(b1))

// =====================================================================
// QKV projection with tf32 tensor cores.
// C[m,n] = hidden[m,:] . W[n,:] + bias[n]; M=15360, K=768, N=3*768.
// Block tile 128x64, BK=32, 256 threads = 8 warps (4x2), warp tile 32x32.
// Double-buffered smem; A_s[128][36], B_s[64][36] (ld=36 => conflict-free
// fragment loads since 36 % 32 == 4).
// =====================================================================
#define GLDA 36
#define GLDB 36
#define A_TILE (128 * GLDA)
#define B_TILE (64 * GLDB)

__global__ __launch_bounds__(256) void qkv_gemm_tc(
    const float* __restrict__ hidden,
    const float* __restrict__ Wq, const float* __restrict__ bq,
    const float* __restrict__ Wk, const float* __restrict__ bk,
    const float* __restrict__ Wv, const float* __restrict__ bv,
    float* __restrict__ out_k, float* __restrict__ out_v)
{
    extern __shared__ float smg[];
    float* As = smg;                 // [2][128][36]
    float* Bs = smg + 2 * A_TILE;    // [2][64][36]

    const int m0  = blockIdx.x * 128;
    const int n0g = blockIdx.y * 64;
    const int mat = n0g / NHID;
    const int n0  = n0g - mat * NHID;

    const float* W  = (mat == 0) ? Wq : (mat == 1) ? Wk : Wv;
    const float* bi = (mat == 0) ? bq : (mat == 1) ? bk : bv;

    const int tid  = threadIdx.x;
    const int lane = tid & 31;
    const int w    = tid >> 5;
    const int wm   = w & 3;          // warp m index (0..3)
    const int wn   = w >> 2;         // warp n index (0..1)
    const int lq   = lane & 3;
    const int lr   = lane >> 2;

    const int ar = tid >> 3;         // 0..31
    const int ac = (tid & 7) << 2;   // 0,4,...,28

    const float* Ag = hidden + (size_t)(m0 + ar) * NHID + ac;
    const float* Bg = W      + (size_t)(n0 + ar) * NHID + ac;

    float4 ra[4];
    float4 rb[2];

    float acc[2][4][4];
#pragma unroll
    for (int mt = 0; mt < 2; mt++)
#pragma unroll
        for (int nt = 0; nt < 4; nt++)
#pragma unroll
            for (int i = 0; i < 4; i++) acc[mt][nt][i] = 0.f;

    // global load into regs
    auto ldglob = [&](int k0) {
#pragma unroll
        for (int i = 0; i < 4; i++)
            ra[i] = *(const float4*)(Ag + (size_t)i * 32 * NHID + k0);
#pragma unroll
        for (int i = 0; i < 2; i++)
            rb[i] = *(const float4*)(Bg + (size_t)i * 32 * NHID + k0);
    };
    // regs -> smem with tf32 rounding
    auto st_smem = [&](int buf) {
        float* A = As + buf * A_TILE;
        float* B = Bs + buf * B_TILE;
#pragma unroll
        for (int i = 0; i < 4; i++) {
            float* p = A + (ar + 32 * i) * GLDA + ac;
            p[0] = f2tf_f(ra[i].x); p[1] = f2tf_f(ra[i].y);
            p[2] = f2tf_f(ra[i].z); p[3] = f2tf_f(ra[i].w);
        }
#pragma unroll
        for (int i = 0; i < 2; i++) {
            float* p = B + (ar + 32 * i) * GLDB + ac;
            p[0] = f2tf_f(rb[i].x); p[1] = f2tf_f(rb[i].y);
            p[2] = f2tf_f(rb[i].z); p[3] = f2tf_f(rb[i].w);
        }
    };
    auto compute = [&](int buf) {
        const float* A = As + buf * A_TILE;
        const float* B = Bs + buf * B_TILE;
#pragma unroll
        for (int ks = 0; ks < 4; ks++) {
            const int kb = ks * 8;
            uint32_t af[2][4];
#pragma unroll
            for (int mt = 0; mt < 2; mt++) {
                const int r = wm * 32 + mt * 16 + lr;
                af[mt][0] = fu(A[r * GLDA + kb + lq]);
                af[mt][1] = fu(A[(r + 8) * GLDA + kb + lq]);
                af[mt][2] = fu(A[r * GLDA + kb + 4 + lq]);
                af[mt][3] = fu(A[(r + 8) * GLDA + kb + 4 + lq]);
            }
            uint32_t bf[4][2];
#pragma unroll
            for (int nt = 0; nt < 4; nt++) {
                const int n = wn * 32 + nt * 8 + lr;
                bf[nt][0] = fu(B[n * GLDB + kb + lq]);
                bf[nt][1] = fu(B[n * GLDB + kb + 4 + lq]);
            }
#pragma unroll
            for (int mt = 0; mt < 2; mt++)
#pragma unroll
                for (int nt = 0; nt < 4; nt++)
                    MMA_TF32(acc[mt][nt], af[mt], bf[nt][0], bf[nt][1]);
        }
    };

    ldglob(0);
    st_smem(0);
    __syncthreads();

    for (int it = 0; it < 24; it++) {
        if (it < 23) ldglob((it + 1) * 32);
        compute(it & 1);
        if (it < 23) st_smem((it + 1) & 1);
        __syncthreads();
    }

    // epilogue: bias + scatter to [b, h, s, d]
    float* dst = (mat == 0) ? g_q : (mat == 1) ? out_k : out_v;
#pragma unroll
    for (int nt = 0; nt < 4; nt++) {
        const int ncol = n0 + wn * 32 + nt * 8 + 2 * lq;
        const float b0 = bi[ncol];
        const float b1 = bi[ncol + 1];
        const int h = ncol >> 6;
        const int d = ncol & 63;
#pragma unroll
        for (int mt = 0; mt < 2; mt++) {
            const int r = wm * 32 + mt * 16 + lr;
#pragma unroll
            for (int half = 0; half < 2; half++) {
                const int m = m0 + r + 8 * half;
                const int b = m >> 6;
                const int s = m & 63;
                const size_t idx = (((size_t)b * NH + h) * NS + s) * HD + d;
                float2 v;
                v.x = acc[mt][nt][2 * half + 0] + b0;
                v.y = acc[mt][nt][2 * half + 1] + b1;
                *(float2*)&dst[idx] = v;
            }
        }
    }
}

// =====================================================================
// Fused cache attention with tf32 mma. One block per (b, h), 256 thr.
// S-phase: warp (mband = w&3, nhalf = w>>2) computes 16x32 of each 64-key
// chunk via m16n8k8 mma (Q frags hoisted). Softmax two-pass on smem score
// matrix (stride 580). PV: same warp tiling, V as col-major B operand.
// =====================================================================
#define SC_LD 580
#define K_LD  68
#define V_LD  72

__global__ __launch_bounds__(256, 1) void attn_tc(
    const float* __restrict__ mask,
    const float* __restrict__ c0k, const float* __restrict__ c0v,
    const float* __restrict__ c1k, const float* __restrict__ c1v,
    const float* __restrict__ kself, const float* __restrict__ vself,
    float* __restrict__ outctx)
{
    extern __shared__ float sm[];
    float* q_s    = sm;                     // [64][68]
    float* kv     = q_s + 64 * K_LD;        // [64][72] (K uses ld 68, V ld 72)
    float* sc     = kv + 64 * V_LD;         // [64][580]
    float* mask_s = sc + 64 * SC_LD;        // [576]
    float* sinv   = mask_s + LTOT;          // [64]

    const int bh   = blockIdx.x;
    const int b    = bh / NH;
    const int h    = bh - b * NH;
    const int tid  = threadIdx.x;
    const int lane = tid & 31;
    const int w    = tid >> 5;
    const int mband = w & 3;
    const int nhalf = w >> 2;
    const int lq    = lane & 3;
    const int lr    = lane >> 2;

    // ---- load Q (tf32-rounded) and mask ----
    {
        const float* qptr = g_q + (size_t)bh * NS * HD;
        const int c4 = (tid & 15) << 2;
        for (int r = tid >> 4; r < 64; r += 16) {
            float4 v = *(const float4*)&qptr[r * HD + c4];
            float* p = q_s + r * K_LD + c4;
            p[0] = f2tf_f(v.x); p[1] = f2tf_f(v.y);
            p[2] = f2tf_f(v.z); p[3] = f2tf_f(v.w);
        }
        for (int i = tid; i < LTOT; i += 256)
            mask_s[i] = mask[(size_t)b * LTOT + i];
    }
    __syncthreads();

    const float* c0kb = c0k + ((size_t)(b & 7) * NH + h) * L0 * HD;
    const float* c0vb = c0v + ((size_t)(b & 7) * NH + h) * L0 * HD;
    const float* c1kb = c1k + (size_t)bh * L1 * HD;
    const float* c1vb = c1v + (size_t)bh * L1 * HD;
    const float* ksb  = kself + (size_t)bh * NS * HD;
    const float* vsb  = vself + (size_t)bh * NS * HD;

    // Q fragments (hoisted: reused across all 9 chunks)
    uint32_t qa[8][4];
#pragma unroll
    for (int ks = 0; ks < 8; ks++) {
        const int r = mband * 16 + lr;
        qa[ks][0] = fu(q_s[r * K_LD + ks * 8 + lq]);
        qa[ks][1] = fu(q_s[(r + 8) * K_LD + ks * 8 + lq]);
        qa[ks][2] = fu(q_s[r * K_LD + ks * 8 + 4 + lq]);
        qa[ks][3] = fu(q_s[(r + 8) * K_LD + ks * 8 + 4 + lq]);
    }

    // ---- phase 1: scores ----
    for (int c = 0; c < NCHUNK; c++) {
        const float* ksrc = (c < 6) ? (c0kb + c * 64 * HD)
                         : (c < 8) ? (c1kb + (c - 6) * 64 * HD)
                                   : ksb;
        __syncthreads();
        {
            const int c4 = (tid & 15) << 2;
            for (int j = tid >> 4; j < 64; j += 16) {
                float4 v = *(const float4*)&ksrc[j * HD + c4];
                float* p = kv + j * K_LD + c4;
                p[0] = f2tf_f(v.x); p[1] = f2tf_f(v.y);
                p[2] = f2tf_f(v.z); p[3] = f2tf_f(v.w);
            }
        }
        __syncthreads();

        float cS[4][4];
#pragma unroll
        for (int nt = 0; nt < 4; nt++)
#pragma unroll
            for (int i = 0; i < 4; i++) cS[nt][i] = 0.f;

#pragma unroll
        for (int ks = 0; ks < 8; ks++) {
#pragma unroll
            for (int nt = 0; nt < 4; nt++) {
                const int n = nhalf * 32 + nt * 8 + lr;
                uint32_t b0 = fu(kv[n * K_LD + ks * 8 + lq]);
                uint32_t b1 = fu(kv[n * K_LD + ks * 8 + 4 + lq]);
                MMA_TF32(cS[nt], qa[ks], b0, b1);
            }
        }
        const int r = mband * 16 + lr;
#pragma unroll
        for (int nt = 0; nt < 4; nt++) {
            const int col = c * 64 + nhalf * 32 + nt * 8 + 2 * lq;
            sc[r * SC_LD + col]           = cS[nt][0] * 0.125f;
            sc[r * SC_LD + col + 1]       = cS[nt][1] * 0.125f;
            sc[(r + 8) * SC_LD + col]     = cS[nt][2] * 0.125f;
            sc[(r + 8) * SC_LD + col + 1] = cS[nt][3] * 0.125f;
        }
    }
    __syncthreads();

    // ---- phase 2: softmax (warp w owns rows 8w..8w+7) ----
    {
        const int r0 = w * 8;
#pragma unroll
        for (int r = 0; r < 8; r++) {
            const int row = r0 + r;
            float vals[18];
            float mx = -1e30f;
#pragma unroll
            for (int i = 0; i < 18; i++) {
                const int col = lane + 32 * i;
                float v = sc[row * SC_LD + col] + mask_s[col];
                vals[i] = v;
                mx = fmaxf(mx, v);
            }
#pragma unroll
            for (int o = 16; o > 0; o >>= 1)
                mx = fmaxf(mx, __shfl_xor_sync(0xFFFFFFFFu, mx, o));
            float s = 0.f;
#pragma unroll
            for (int i = 0; i < 18; i++) {
                const int col = lane + 32 * i;
                float p = __expf(vals[i] - mx);
                sc[row * SC_LD + col] = p;
                s += p;
            }
#pragma unroll
            for (int o = 16; o > 0; o >>= 1)
                s += __shfl_xor_sync(0xFFFFFFFFu, s, o);
            if (lane == 0) sinv[row] = 1.f / s;
        }
    }

    // ---- phase 3: ctx = P @ V ----
    float ctx[4][4];
#pragma unroll
    for (int nt = 0; nt < 4; nt++)
#pragma unroll
        for (int i = 0; i < 4; i++) ctx[nt][i] = 0.f;

    for (int c = 0; c < NCHUNK; c++) {
        const float* vsrc = (c < 6) ? (c0vb + c * 64 * HD)
                         : (c < 8) ? (c1vb + (c - 6) * 64 * HD)
                                   : vsb;
        __syncthreads();
        {
            const int c4 = (tid & 15) << 2;
            for (int j = tid >> 4; j < 64; j += 16) {
                float4 v = *(const float4*)&vsrc[j * HD + c4];
                float* p = kv + j * V_LD + c4;
                p[0] = f2tf_f(v.x); p[1] = f2tf_f(v.y);
                p[2] = f2tf_f(v.z); p[3] = f2tf_f(v.w);
            }
        }
        __syncthreads();

        const int r = mband * 16 + lr;
#pragma unroll
        for (int ks = 0; ks < 8; ks++) {
            const int kcol = c * 64 + ks * 8;
            uint32_t pa[4];
            pa[0] = f2tf(sc[r * SC_LD + kcol + lq]);
            pa[1] = f2tf(sc[(r + 8) * SC_LD + kcol + lq]);
            pa[2] = f2tf(sc[r * SC_LD + kcol + 4 + lq]);
            pa[3] = f2tf(sc[(r + 8) * SC_LD + kcol + 4 + lq]);
#pragma unroll
            for (int nt = 0; nt < 4; nt++) {
                const int n = nhalf * 32 + nt * 8 + lr;
                uint32_t b0 = fu(kv[(ks * 8 + lq) * V_LD + n]);
                uint32_t b1 = fu(kv[(ks * 8 + 4 + lq) * V_LD + n]);
                MMA_TF32(ctx[nt], pa, b0, b1);
            }
        }
    }

    // ---- write ctx -> out[b, s, h*64 + d] ----
    {
        const int r = mband * 16 + lr;
        const float s0 = sinv[r];
        const float s1 = sinv[r + 8];
#pragma unroll
        for (int nt = 0; nt < 4; nt++) {
            const int dcol = nhalf * 32 + nt * 8 + 2 * lq;
            float2 v0, v1;
            v0.x = ctx[nt][0] * s0; v0.y = ctx[nt][1] * s0;
            v1.x = ctx[nt][2] * s1; v1.y = ctx[nt][3] * s1;
            *(float2*)&outctx[((size_t)b * NS + r) * NHID + h * HD + dcol]     = v0;
            *(float2*)&outctx[((size_t)b * NS + r + 8) * NHID + h * HD + dcol] = v1;
        }
    }
}

// =====================================================================
// Host launcher
// =====================================================================
extern "C" void kernel_launch(void* const* d_in, const int* in_sizes, int n_in,
                              void* d_out, int out_size)
{
    const float* hidden = (const float*)d_in[0];
    const float* mask   = (const float*)d_in[1];
    const float* Wq     = (const float*)d_in[2];
    const float* bq     = (const float*)d_in[3];
    const float* Wk     = (const float*)d_in[4];
    const float* bk     = (const float*)d_in[5];
    const float* Wv     = (const float*)d_in[6];
    const float* bv     = (const float*)d_in[7];
    const float* c0k    = (const float*)d_in[8];
    const float* c0v    = (const float*)d_in[9];
    const float* c1k    = (const float*)d_in[10];
    const float* c1v    = (const float*)d_in[11];

    float* out   = (float*)d_out;
    const size_t sect = (size_t)NB * NS * NHID;
    float* out_k = out + sect;
    float* out_v = out + 2 * sect;

    const int gemm_smem = (2 * A_TILE + 2 * B_TILE) * 4;                   // 55296
    const int attn_smem = (64 * K_LD + 64 * V_LD + 64 * SC_LD + LTOT + 64) * 4; // 186880

    static int configured = 0;
    cudaFuncSetAttribute(qkv_gemm_tc,
                         cudaFuncAttributeMaxDynamicSharedMemorySize, gemm_smem);
    cudaFuncSetAttribute(attn_tc,
                         cudaFuncAttributeMaxDynamicSharedMemorySize, attn_smem);
    (void)configured;

    dim3 ggrid(NB * NS / 128, 3 * NHID / 64);   // (120, 36)
    qkv_gemm_tc<<<ggrid, 256, gemm_smem>>>(hidden, Wq, bq, Wk, bk, Wv, bv,
                                           out_k, out_v);

    attn_tc<<<NB * NH, 256, attn_smem>>>(mask, c0k, c0v, c1k, c1v,
                                         out_k, out_v, out);
}

// round 3
// speedup vs baseline: 3.4914x; 1.5353x over previous
#include <cuda_runtime.h>
#include <cstdint>

// ---------------- problem constants (fixed by the dataset) ----------------
#define NB    240
#define NS    64
#define NHID  768
#define NH    12
#define HD    64
#define L0    384
#define L1    128
#define LTOT  576
#define NCHUNK 9

// q scratch in [b, h, s, d] layout
__device__ float g_q[(size_t)NB * NH * NS * HD];

// ---------------- tf32 helpers ----------------
__device__ __forceinline__ uint32_t f2tf(float x) {
    uint32_t r;
    asm("cvt.rna.tf32.f32 %0, %1;" : "=r"(r) : "f"(x));
    return r;
}
__device__ __forceinline__ float f2tf_f(float x) { return __uint_as_float(f2tf(x)); }
__device__ __forceinline__ uint32_t fu(float x) { return __float_as_uint(x); }

#define MMA_TF32(c, a, b0, b1)                                              \
    asm volatile(                                                           \
        "mma.sync.aligned.m16n8k8.row.col.f32.tf32.tf32.f32 "               \
        "{%0,%1,%2,%3}, {%4,%5,%6,%7}, {%8,%9}, {%0,%1,%2,%3};\n"           \
        : "+f"((c)[0]), "+f"((c)[1]), "+f"((c)[2]), "+f"((c)[3])            \
        : "r"((a)[0]), "r"((a)[1]), "r"((a)[2]), "r"((a)[3]),               \
          "r"(b0), "r"(b1))

__device__ __forceinline__ void cp16(float* dst, const float* src) {
    uint32_t d = (uint32_t)__cvta_generic_to_shared(dst);
    asm volatile("cp.async.cg.shared.global [%0], [%1], 16;\n"
                 :: "r"(d), "l"(src));
}
__device__ __forceinline__ void cp_commit() {
    asm volatile("cp.async.commit_group;\n");
}
template <int N> __device__ __forceinline__ void cp_wait() {
    asm volatile("cp.async.wait_group %0;\n" :: "n"(N));
}

// =====================================================================
// QKV projection with tf32 tensor cores (unchanged from round 2).
// =====================================================================
#define GLDA 36
#define GLDB 36
#define A_TILE (128 * GLDA)
#define B_TILE (64 * GLDB)

__global__ __launch_bounds__(256) void qkv_gemm_tc(
    const float* __restrict__ hidden,
    const float* __restrict__ Wq, const float* __restrict__ bq,
    const float* __restrict__ Wk, const float* __restrict__ bk,
    const float* __restrict__ Wv, const float* __restrict__ bv,
    float* __restrict__ out_k, float* __restrict__ out_v)
{
    extern __shared__ float smg[];
    float* As = smg;
    float* Bs = smg + 2 * A_TILE;

    const int m0  = blockIdx.x * 128;
    const int n0g = blockIdx.y * 64;
    const int mat = n0g / NHID;
    const int n0  = n0g - mat * NHID;

    const float* W  = (mat == 0) ? Wq : (mat == 1) ? Wk : Wv;
    const float* bi = (mat == 0) ? bq : (mat == 1) ? bk : bv;

    const int tid  = threadIdx.x;
    const int lane = tid & 31;
    const int w    = tid >> 5;
    const int wm   = w & 3;
    const int wn   = w >> 2;
    const int lq   = lane & 3;
    const int lr   = lane >> 2;

    const int ar = tid >> 3;
    const int ac = (tid & 7) << 2;

    const float* Ag = hidden + (size_t)(m0 + ar) * NHID + ac;
    const float* Bg = W      + (size_t)(n0 + ar) * NHID + ac;

    float4 ra[4];
    float4 rb[2];

    float acc[2][4][4];
#pragma unroll
    for (int mt = 0; mt < 2; mt++)
#pragma unroll
        for (int nt = 0; nt < 4; nt++)
#pragma unroll
            for (int i = 0; i < 4; i++) acc[mt][nt][i] = 0.f;

    auto ldglob = [&](int k0) {
#pragma unroll
        for (int i = 0; i < 4; i++)
            ra[i] = *(const float4*)(Ag + (size_t)i * 32 * NHID + k0);
#pragma unroll
        for (int i = 0; i < 2; i++)
            rb[i] = *(const float4*)(Bg + (size_t)i * 32 * NHID + k0);
    };
    auto st_smem = [&](int buf) {
        float* A = As + buf * A_TILE;
        float* B = Bs + buf * B_TILE;
#pragma unroll
        for (int i = 0; i < 4; i++) {
            float* p = A + (ar + 32 * i) * GLDA + ac;
            p[0] = f2tf_f(ra[i].x); p[1] = f2tf_f(ra[i].y);
            p[2] = f2tf_f(ra[i].z); p[3] = f2tf_f(ra[i].w);
        }
#pragma unroll
        for (int i = 0; i < 2; i++) {
            float* p = B + (ar + 32 * i) * GLDB + ac;
            p[0] = f2tf_f(rb[i].x); p[1] = f2tf_f(rb[i].y);
            p[2] = f2tf_f(rb[i].z); p[3] = f2tf_f(rb[i].w);
        }
    };
    auto compute = [&](int buf) {
        const float* A = As + buf * A_TILE;
        const float* B = Bs + buf * B_TILE;
#pragma unroll
        for (int ks = 0; ks < 4; ks++) {
            const int kb = ks * 8;
            uint32_t af[2][4];
#pragma unroll
            for (int mt = 0; mt < 2; mt++) {
                const int r = wm * 32 + mt * 16 + lr;
                af[mt][0] = fu(A[r * GLDA + kb + lq]);
                af[mt][1] = fu(A[(r + 8) * GLDA + kb + lq]);
                af[mt][2] = fu(A[r * GLDA + kb + 4 + lq]);
                af[mt][3] = fu(A[(r + 8) * GLDA + kb + 4 + lq]);
            }
            uint32_t bf[4][2];
#pragma unroll
            for (int nt = 0; nt < 4; nt++) {
                const int n = wn * 32 + nt * 8 + lr;
                bf[nt][0] = fu(B[n * GLDB + kb + lq]);
                bf[nt][1] = fu(B[n * GLDB + kb + 4 + lq]);
            }
#pragma unroll
            for (int mt = 0; mt < 2; mt++)
#pragma unroll
                for (int nt = 0; nt < 4; nt++)
                    MMA_TF32(acc[mt][nt], af[mt], bf[nt][0], bf[nt][1]);
        }
    };

    ldglob(0);
    st_smem(0);
    __syncthreads();

    for (int it = 0; it < 24; it++) {
        if (it < 23) ldglob((it + 1) * 32);
        compute(it & 1);
        if (it < 23) st_smem((it + 1) & 1);
        __syncthreads();
    }

    float* dst = (mat == 0) ? g_q : (mat == 1) ? out_k : out_v;
#pragma unroll
    for (int nt = 0; nt < 4; nt++) {
        const int ncol = n0 + wn * 32 + nt * 8 + 2 * lq;
        const float b0 = bi[ncol];
        const float b1 = bi[ncol + 1];
        const int h = ncol >> 6;
        const int d = ncol & 63;
#pragma unroll
        for (int mt = 0; mt < 2; mt++) {
            const int r = wm * 32 + mt * 16 + lr;
#pragma unroll
            for (int half = 0; half < 2; half++) {
                const int m = m0 + r + 8 * half;
                const int b = m >> 6;
                const int s = m & 63;
                const size_t idx = (((size_t)b * NH + h) * NS + s) * HD + d;
                float2 v;
                v.x = acc[mt][nt][2 * half + 0] + b0;
                v.y = acc[mt][nt][2 * half + 1] + b1;
                *(float2*)&dst[idx] = v;
            }
        }
    }
}

// =====================================================================
// Flash cache attention, tf32 mma. One block = one (b,h), 128 threads
// = 4 warps; warp w owns q-rows 16w..16w+15 across full key extent.
// K/V 64-key chunks double-buffered via cp.async. Online softmax; P
// stays in registers (C->A fragment remap via quad shuffles).
// =====================================================================
#define KV_LD 68
#define KV_TILE (64 * KV_LD)

__global__ __launch_bounds__(128, 3) void attn_flash(
    const float* __restrict__ mask,
    const float* __restrict__ c0k, const float* __restrict__ c0v,
    const float* __restrict__ c1k, const float* __restrict__ c1v,
    const float* __restrict__ kself, const float* __restrict__ vself,
    float* __restrict__ outctx)
{
    extern __shared__ float sm[];
    float* kbuf   = sm;                       // [2][64][68]
    float* vbuf   = kbuf + 2 * KV_TILE;       // [2][64][68]
    float* mask_s = vbuf + 2 * KV_TILE;       // [576]

    const int bh   = blockIdx.x;
    const int b    = bh / NH;
    const int h    = bh - b * NH;
    const int tid  = threadIdx.x;
    const int lane = tid & 31;
    const int w    = tid >> 5;
    const int lq   = lane & 3;
    const int lr   = lane >> 2;
    const int qb   = lane & 28;               // quad base lane

    const float* c0kb = c0k + ((size_t)(b & 7) * NH + h) * L0 * HD;
    const float* c0vb = c0v + ((size_t)(b & 7) * NH + h) * L0 * HD;
    const float* c1kb = c1k + (size_t)bh * L1 * HD;
    const float* c1vb = c1v + (size_t)bh * L1 * HD;
    const float* ksb  = kself + (size_t)bh * NS * HD;
    const float* vsb  = vself + (size_t)bh * NS * HD;

    auto ksrc_of = [&](int c) -> const float* {
        return (c < 6) ? (c0kb + c * 64 * HD)
             : (c < 8) ? (c1kb + (c - 6) * 64 * HD) : ksb;
    };
    auto vsrc_of = [&](int c) -> const float* {
        return (c < 6) ? (c0vb + c * 64 * HD)
             : (c < 8) ? (c1vb + (c - 6) * 64 * HD) : vsb;
    };

    // async tile load: 64x64 floats -> buf stride KV_LD. 128 threads,
    // thread: row tid>>1, 32-col half (tid&1), 8 x 16B each.
    auto load_tile = [&](float* buf, const float* src) {
        const int r  = tid >> 1;
        const int c0 = (tid & 1) * 32;
        float* d = buf + r * KV_LD + c0;
        const float* s = src + r * HD + c0;
#pragma unroll
        for (int i = 0; i < 8; i++) cp16(d + 4 * i, s + 4 * i);
    };

    // ---- prologue: stage Q into kbuf[1]; chunk0 into buf0; mask ----
    load_tile(kbuf + KV_TILE, g_q + (size_t)bh * NS * HD);
    cp_commit();
    load_tile(kbuf, ksrc_of(0));
    load_tile(vbuf, vsrc_of(0));
    cp_commit();

    for (int i = tid; i < LTOT; i += 128)
        mask_s[i] = mask[(size_t)b * LTOT + i];

    cp_wait<1>();            // Q group done
    __syncthreads();

    // Q fragments (rows w*16 + lr / +8), tf32-rounded, reused all chunks
    uint32_t qa[8][4];
    {
        const float* qs = kbuf + KV_TILE;
        const int r = w * 16 + lr;
#pragma unroll
        for (int ks = 0; ks < 8; ks++) {
            qa[ks][0] = f2tf(qs[r * KV_LD + ks * 8 + lq]);
            qa[ks][1] = f2tf(qs[(r + 8) * KV_LD + ks * 8 + lq]);
            qa[ks][2] = f2tf(qs[r * KV_LD + ks * 8 + 4 + lq]);
            qa[ks][3] = f2tf(qs[(r + 8) * KV_LD + ks * 8 + 4 + lq]);
        }
    }
    __syncthreads();         // Q reads done before chunk1 overwrites kbuf[1]

    // online-softmax state
    float m0 = -1e30f, m1 = -1e30f;    // running max, rows lr / lr+8
    float l0 = 0.f,    l1 = 0.f;       // running sum
    float o[8][4];
#pragma unroll
    for (int dt = 0; dt < 8; dt++)
#pragma unroll
        for (int i = 0; i < 4; i++) o[dt][i] = 0.f;

    for (int c = 0; c < NCHUNK; c++) {
        if (c < NCHUNK - 1) {
            float* kb = kbuf + ((c + 1) & 1) * KV_TILE;
            float* vb = vbuf + ((c + 1) & 1) * KV_TILE;
            load_tile(kb, ksrc_of(c + 1));
            load_tile(vb, vsrc_of(c + 1));
            cp_commit();
            cp_wait<1>();
        } else {
            cp_wait<0>();
        }
        __syncthreads();

        const float* K = kbuf + (c & 1) * KV_TILE;
        const float* V = vbuf + (c & 1) * KV_TILE;

        // ---- S = Q K^T (16x64 per warp) ----
        float cS[8][4];
#pragma unroll
        for (int nt = 0; nt < 8; nt++)
#pragma unroll
            for (int i = 0; i < 4; i++) cS[nt][i] = 0.f;

#pragma unroll
        for (int ks = 0; ks < 8; ks++) {
#pragma unroll
            for (int nt = 0; nt < 8; nt++) {
                const int n = nt * 8 + lr;
                uint32_t b0 = f2tf(K[n * KV_LD + ks * 8 + lq]);
                uint32_t b1 = f2tf(K[n * KV_LD + ks * 8 + 4 + lq]);
                MMA_TF32(cS[nt], qa[ks], b0, b1);
            }
        }

        // ---- mask + scale + row max (this chunk) ----
        float cm0 = -1e30f, cm1 = -1e30f;
#pragma unroll
        for (int nt = 0; nt < 8; nt++) {
            const int col = c * 64 + nt * 8 + 2 * lq;
            const float mv0 = mask_s[col];
            const float mv1 = mask_s[col + 1];
            cS[nt][0] = cS[nt][0] * 0.125f + mv0;
            cS[nt][1] = cS[nt][1] * 0.125f + mv1;
            cS[nt][2] = cS[nt][2] * 0.125f + mv0;
            cS[nt][3] = cS[nt][3] * 0.125f + mv1;
            cm0 = fmaxf(cm0, fmaxf(cS[nt][0], cS[nt][1]));
            cm1 = fmaxf(cm1, fmaxf(cS[nt][2], cS[nt][3]));
        }
#pragma unroll
        for (int off = 1; off <= 2; off <<= 1) {
            cm0 = fmaxf(cm0, __shfl_xor_sync(0xFFFFFFFFu, cm0, off));
            cm1 = fmaxf(cm1, __shfl_xor_sync(0xFFFFFFFFu, cm1, off));
        }

        const float mn0 = fmaxf(m0, cm0);
        const float mn1 = fmaxf(m1, cm1);
        const float a0  = __expf(m0 - mn0);
        const float a1  = __expf(m1 - mn1);
        m0 = mn0; m1 = mn1;

        // ---- exp + row sums ----
        float s0 = 0.f, s1 = 0.f;
#pragma unroll
        for (int nt = 0; nt < 8; nt++) {
            cS[nt][0] = __expf(cS[nt][0] - mn0);
            cS[nt][1] = __expf(cS[nt][1] - mn0);
            cS[nt][2] = __expf(cS[nt][2] - mn1);
            cS[nt][3] = __expf(cS[nt][3] - mn1);
            s0 += cS[nt][0] + cS[nt][1];
            s1 += cS[nt][2] + cS[nt][3];
        }
#pragma unroll
        for (int off = 1; off <= 2; off <<= 1) {
            s0 += __shfl_xor_sync(0xFFFFFFFFu, s0, off);
            s1 += __shfl_xor_sync(0xFFFFFFFFu, s1, off);
        }
        l0 = l0 * a0 + s0;
        l1 = l1 * a1 + s1;

        // ---- rescale O ----
#pragma unroll
        for (int dt = 0; dt < 8; dt++) {
            o[dt][0] *= a0; o[dt][1] *= a0;
            o[dt][2] *= a1; o[dt][3] *= a1;
        }

        // ---- PV: remap P C-frag -> A-frag via quad shuffles, mma ----
#pragma unroll
        for (int kt = 0; kt < 8; kt++) {
            const int sl0 = qb + (lq >> 1);
            const int sl1 = sl0 + 2;
            const bool odd = lq & 1;
            float t00 = __shfl_sync(0xFFFFFFFFu, cS[kt][0], sl0);
            float t10 = __shfl_sync(0xFFFFFFFFu, cS[kt][1], sl0);
            float t01 = __shfl_sync(0xFFFFFFFFu, cS[kt][0], sl1);
            float t11 = __shfl_sync(0xFFFFFFFFu, cS[kt][1], sl1);
            float u00 = __shfl_sync(0xFFFFFFFFu, cS[kt][2], sl0);
            float u10 = __shfl_sync(0xFFFFFFFFu, cS[kt][3], sl0);
            float u01 = __shfl_sync(0xFFFFFFFFu, cS[kt][2], sl1);
            float u11 = __shfl_sync(0xFFFFFFFFu, cS[kt][3], sl1);
            uint32_t pa[4];
            pa[0] = f2tf(odd ? t10 : t00);
            pa[1] = f2tf(odd ? u10 : u00);
            pa[2] = f2tf(odd ? t11 : t01);
            pa[3] = f2tf(odd ? u11 : u01);
#pragma unroll
            for (int dt = 0; dt < 8; dt++) {
                uint32_t b0 = f2tf(V[(kt * 8 + lq) * KV_LD + dt * 8 + lr]);
                uint32_t b1 = f2tf(V[(kt * 8 + 4 + lq) * KV_LD + dt * 8 + lr]);
                MMA_TF32(o[dt], pa, b0, b1);
            }
        }
        __syncthreads();    // all warps done with buf[c&1] before next issue
    }

    // ---- epilogue: normalize + write out[b, s, h*64 + d] ----
    {
        const float r0 = 1.f / l0;
        const float r1 = 1.f / l1;
        const int r = w * 16 + lr;
        float* ob0 = outctx + ((size_t)b * NS + r) * NHID + h * HD;
        float* ob1 = outctx + ((size_t)b * NS + r + 8) * NHID + h * HD;
#pragma unroll
        for (int dt = 0; dt < 8; dt++) {
            const int dcol = dt * 8 + 2 * lq;
            float2 v0, v1;
            v0.x = o[dt][0] * r0; v0.y = o[dt][1] * r0;
            v1.x = o[dt][2] * r1; v1.y = o[dt][3] * r1;
            *(float2*)&ob0[dcol] = v0;
            *(float2*)&ob1[dcol] = v1;
        }
    }
}

// =====================================================================
// Host launcher
// =====================================================================
extern "C" void kernel_launch(void* const* d_in, const int* in_sizes, int n_in,
                              void* d_out, int out_size)
{
    const float* hidden = (const float*)d_in[0];
    const float* mask   = (const float*)d_in[1];
    const float* Wq     = (const float*)d_in[2];
    const float* bq     = (const float*)d_in[3];
    const float* Wk     = (const float*)d_in[4];
    const float* bk     = (const float*)d_in[5];
    const float* Wv     = (const float*)d_in[6];
    const float* bv     = (const float*)d_in[7];
    const float* c0k    = (const float*)d_in[8];
    const float* c0v    = (const float*)d_in[9];
    const float* c1k    = (const float*)d_in[10];
    const float* c1v    = (const float*)d_in[11];

    float* out   = (float*)d_out;
    const size_t sect = (size_t)NB * NS * NHID;
    float* out_k = out + sect;
    float* out_v = out + 2 * sect;

    const int gemm_smem = (2 * A_TILE + 2 * B_TILE) * 4;          // 55296
    const int attn_smem = (4 * KV_TILE + LTOT) * 4;               // 71936

    cudaFuncSetAttribute(qkv_gemm_tc,
                         cudaFuncAttributeMaxDynamicSharedMemorySize, gemm_smem);
    cudaFuncSetAttribute(attn_flash,
                         cudaFuncAttributeMaxDynamicSharedMemorySize, attn_smem);

    dim3 ggrid(NB * NS / 128, 3 * NHID / 64);   // (120, 36)
    qkv_gemm_tc<<<ggrid, 256, gemm_smem>>>(hidden, Wq, bq, Wk, bk, Wv, bv,
                                           out_k, out_v);

    attn_flash<<<NB * NH, 128, attn_smem>>>(mask, c0k, c0v, c1k, c1v,
                                            out_k, out_v, out);
}